// round 4
// baseline (speedup 1.0000x reference)
#include <cuda_runtime.h>
#include <math.h>

#define JN 23
#define VMAX 400000

// Scratch (device globals — no allocation allowed)
__device__ float4 g_verts[VMAX];    // posed verts (xyz, pad)
__device__ float4 g_nsum[VMAX];     // neighbor sum xyz + degree in .w

// ---------------------------------------------------------------------------
// Rig math, computed redundantly per block inside k_skin by warp 0:
// lanes 0..22 do Rodrigues in parallel; lane 0 walks the serial chain.
// Result: sA[j*12 + e] = 3x4 skinning matrix A_j, soff = rdis + disp.
// ---------------------------------------------------------------------------
__device__ __forceinline__ void rig_warp0(
    const float* __restrict__ joints,
    const float* __restrict__ j0in, const float* __restrict__ j2in,
    const float* __restrict__ j3in, const float* __restrict__ j4in,
    const float* __restrict__ j5in,
    const float* __restrict__ disp, const float* __restrict__ rdis,
    float* sM /* [JN*12] scratch */, float* sA /* [JN*12] out */, float* soff)
{
    const int lane = threadIdx.x;   // caller guarantees threadIdx.x < 32
    const float HALF_PI = 1.5707963267948966f;
    const int PAR[JN] = {-1,0,1,1,3,4,5,4,7,4,9,1,11,12,13,12,15,12,17,0,19,0,21};

    if (lane < JN) {
        float px = 0.f, py = 0.f, pz = 0.f;
        if (lane == 0)       { px = j0in[0]; py = j0in[1]; pz = j0in[2]; }
        else if (lane == 3)  { px = HALF_PI*tanhf(j2in[0]); py = HALF_PI*tanhf(j2in[1]); pz = HALF_PI*tanhf(j2in[2]); }
        else if (lane == 4)  { px = HALF_PI*tanhf(j3in[0]); py = HALF_PI*tanhf(j3in[1]); pz = HALF_PI*tanhf(j3in[2]); }
        else if (lane == 11) { px = HALF_PI*tanhf(j4in[0]); py = HALF_PI*tanhf(j4in[1]); pz = HALF_PI*tanhf(j4in[2]); }
        else if (lane == 12) { px = HALF_PI*tanhf(j5in[0]); py = HALF_PI*tanhf(j5in[1]); pz = HALF_PI*tanhf(j5in[2]); }

        float ang = sqrtf(px*px + py*py + pz*pz) + 1e-8f;
        float ax = px/ang, ay = py/ang, az = pz/ang;
        float K[9]  = {0.f, -az, ay,  az, 0.f, -ax,  -ay, ax, 0.f};
        float K2[9];
        #pragma unroll
        for (int r = 0; r < 3; r++)
            #pragma unroll
            for (int c = 0; c < 3; c++) {
                float s = 0.f;
                #pragma unroll
                for (int t = 0; t < 3; t++) s += K[r*3+t] * K[t*3+c];
                K2[r*3+c] = s;
            }
        float sn = sinf(ang), cs = cosf(ang);
        float R[9];
        #pragma unroll
        for (int e = 0; e < 9; e++) {
            float eye = (e == 0 || e == 4 || e == 8) ? 1.0f : 0.0f;
            R[e] = eye + sn * K[e] + (1.0f - cs) * K2[e];
        }
        float rel[3];
        #pragma unroll
        for (int k = 0; k < 3; k++) {
            rel[k] = joints[lane*3 + k];
            if (lane > 0) rel[k] -= joints[PAR[lane]*3 + k];
        }
        sM[lane*12+0]=R[0]; sM[lane*12+1]=R[1]; sM[lane*12+2] =R[2]; sM[lane*12+3] =rel[0];
        sM[lane*12+4]=R[3]; sM[lane*12+5]=R[4]; sM[lane*12+6] =R[5]; sM[lane*12+7] =rel[1];
        sM[lane*12+8]=R[6]; sM[lane*12+9]=R[7]; sM[lane*12+10]=R[8]; sM[lane*12+11]=rel[2];
    }
    __syncwarp();

    if (lane == 0) {
        float chain[JN][12];
        #pragma unroll
        for (int e = 0; e < 12; e++) chain[0][e] = sM[e];
        for (int i = 1; i < JN; i++) {
            const float* P = chain[PAR[i]];
            const float* M = sM + i*12;
            float* C = chain[i];
            #pragma unroll
            for (int r = 0; r < 3; r++) {
                #pragma unroll
                for (int cc = 0; cc < 3; cc++) {
                    C[r*4+cc] = P[r*4+0]*M[0*4+cc] + P[r*4+1]*M[1*4+cc] + P[r*4+2]*M[2*4+cc];
                }
                C[r*4+3] = P[r*4+0]*M[3] + P[r*4+1]*M[7] + P[r*4+2]*M[11] + P[r*4+3];
            }
        }
        for (int i = 0; i < JN; i++) {
            float jx = joints[i*3+0], jy = joints[i*3+1], jz = joints[i*3+2];
            #pragma unroll
            for (int r = 0; r < 3; r++) {
                float corr = chain[i][r*4+0]*jx + chain[i][r*4+1]*jy + chain[i][r*4+2]*jz;
                sA[i*12 + r*4 + 0] = chain[i][r*4+0];
                sA[i*12 + r*4 + 1] = chain[i][r*4+1];
                sA[i*12 + r*4 + 2] = chain[i][r*4+2];
                sA[i*12 + r*4 + 3] = chain[i][r*4+3] - corr;
            }
        }
    }
    if (lane < 3) soff[lane] = rdis[lane] + disp[lane];
}

// ---------------------------------------------------------------------------
// Kernel 1 (fused rig + skinning): warp 0 computes the rig while warps 1..7
// stage the skinning-weight tile into shared memory (coalesced float4).
// ---------------------------------------------------------------------------
#define SKIN_B 256
__global__ void __launch_bounds__(SKIN_B)
k_skin(const float* __restrict__ verts_in,
       const float* __restrict__ skin,
       const float* __restrict__ joints,
       const float* __restrict__ j0in, const float* __restrict__ j2in,
       const float* __restrict__ j3in, const float* __restrict__ j4in,
       const float* __restrict__ j5in,
       const float* __restrict__ disp, const float* __restrict__ rdis,
       float* __restrict__ out,
       float* __restrict__ lap_slot,
       int V)
{
    __shared__ __align__(16) float tile[SKIN_B * JN];  // 23.5 KB, stride-23 reads
    __shared__ float sA[JN * 12];
    __shared__ float sM[JN * 12];
    __shared__ float soff[3];

    const int base = blockIdx.x * SKIN_B;
    const int nv   = min(SKIN_B, V - base);

    if (threadIdx.x < 32) {
        // warp 0: rig math (serial chain latency hides under tile staging)
        rig_warp0(joints, j0in, j2in, j3in, j4in, j5in, disp, rdis, sM, sA, soff);
    } else {
        // warps 1..7: stage the weight tile
        const int t = threadIdx.x - 32;
        const int NT = SKIN_B - 32;
        if (nv == SKIN_B) {
            const float4* src = reinterpret_cast<const float4*>(skin + (size_t)base * JN);
            float4* dst = reinterpret_cast<float4*>(tile);
            #pragma unroll
            for (int i = t; i < SKIN_B * JN / 4; i += NT) dst[i] = src[i];
        } else {
            const float* src = skin + (size_t)base * JN;
            for (int i = t; i < nv * JN; i += NT) tile[i] = src[i];
        }
    }
    __syncthreads();

    const int v = base + threadIdx.x;
    if (v == 0) *lap_slot = 0.0f;
    if (threadIdx.x >= nv) return;

    float T[12];
    #pragma unroll
    for (int e = 0; e < 12; e++) T[e] = 0.0f;

    const float* s = tile + threadIdx.x * JN;
    #pragma unroll
    for (int j = 0; j < JN; j++) {
        float w = s[j];
        #pragma unroll
        for (int e = 0; e < 12; e++) T[e] += w * sA[j*12 + e];
    }

    float x = verts_in[3*v+0], y = verts_in[3*v+1], z = verts_in[3*v+2];
    float px = T[0]*x + T[1]*y + T[2] *z + T[3]  + soff[0];
    float py = T[4]*x + T[5]*y + T[6] *z + T[7]  + soff[1];
    float pz = T[8]*x + T[9]*y + T[10]*z + T[11] + soff[2];

    g_verts[v] = make_float4(px, py, pz, 0.0f);
    g_nsum[v]  = make_float4(0.0f, 0.0f, 0.0f, 0.0f);

    out[3*v+0] = px;
    out[3*v+1] = py;
    out[3*v+2] = pz;
}

// ---------------------------------------------------------------------------
// Kernel 2 (fused): face scatter (LTS-atomic bound) interleaved with the
// batch broadcast (DRAM bound) — block-type by blockIdx.x % 4.
// ---------------------------------------------------------------------------
__device__ __forceinline__ void red4(float4* p, float x, float y, float z, float w)
{
    asm volatile("red.global.add.v4.f32 [%0], {%1, %2, %3, %4};"
                 :: "l"(p), "f"(x), "f"(y), "f"(z), "f"(w) : "memory");
}

__global__ void __launch_bounds__(256)
k_faces_bcast(const int* __restrict__ faces, int F,
              float* __restrict__ out, int V, int B)
{
    if ((blockIdx.x & 3) == 0) {
        // ---- copy block: broadcast batch 0 -> batches 1..B-1 ----
        const int cid = blockIdx.x >> 2;
        const int n4 = (V * 3) / 4;
        const int i = cid * 256 + threadIdx.x;
        if (i < n4) {
            float4 val = __ldg(reinterpret_cast<const float4*>(out) + i);
            const size_t stride4 = (size_t)(V * 3) / 4;
            float4* o = reinterpret_cast<float4*>(out);
            #pragma unroll 4
            for (int b = 1; b < B; b++) o[(size_t)b * stride4 + i] = val;
        }
    } else {
        // ---- face block ----
        const int fid = blockIdx.x - ((int)blockIdx.x >> 2) - 1;
        const int f = fid * 256 + threadIdx.x;
        if (f < F) {
            int a = __ldg(&faces[3*f+0]);
            int b = __ldg(&faces[3*f+1]);
            int c = __ldg(&faces[3*f+2]);
            float4 va = __ldg(&g_verts[a]);
            float4 vb = __ldg(&g_verts[b]);
            float4 vc = __ldg(&g_verts[c]);
            red4(&g_nsum[a], vb.x + vc.x, vb.y + vc.y, vb.z + vc.z, 2.0f);
            red4(&g_nsum[b], va.x + vc.x, va.y + vc.y, va.z + vc.z, 2.0f);
            red4(&g_nsum[c], va.x + vb.x, va.y + vb.y, va.z + vb.z, 2.0f);
        }
    }
}

// ---------------------------------------------------------------------------
// Kernel 3: Laplacian reduction. 2 vertices per thread (v, v+half) with all
// four loads issued up-front (MLP=4); 782 blocks keeps occupancy high.
// ---------------------------------------------------------------------------
__global__ void __launch_bounds__(256)
k_lap(float* __restrict__ lap_slot, int V)
{
    const int half = (V + 1) >> 1;
    const int v1 = blockIdx.x * blockDim.x + threadIdx.x;
    const int v2 = v1 + half;

    float s = 0.0f;
    if (v1 < half) {
        float4 p1 = __ldg(&g_verts[v1]);
        float4 n1 = __ldg(&g_nsum[v1]);
        bool ok2 = (v2 < V);
        float4 p2 = ok2 ? __ldg(&g_verts[v2]) : make_float4(0,0,0,0);
        float4 n2 = ok2 ? __ldg(&g_nsum[v2]) : make_float4(0,0,0,1);

        float d1 = fmaxf(n1.w, 1.0f);
        float lx = p1.x - n1.x / d1;
        float ly = p1.y - n1.y / d1;
        float lz = p1.z - n1.z / d1;
        s = lx*lx + ly*ly + lz*lz;

        float d2 = fmaxf(n2.w, 1.0f);
        float mx = p2.x - n2.x / d2;
        float my = p2.y - n2.y / d2;
        float mz = p2.z - n2.z / d2;
        s += mx*mx + my*my + mz*mz;
    }

    #pragma unroll
    for (int o = 16; o > 0; o >>= 1) s += __shfl_down_sync(0xffffffffu, s, o);

    __shared__ float ws[8];
    int lane = threadIdx.x & 31, w = threadIdx.x >> 5;
    if (lane == 0) ws[w] = s;
    __syncthreads();
    if (w == 0) {
        s = (lane < (int)(blockDim.x >> 5)) ? ws[lane] : 0.0f;
        #pragma unroll
        for (int o = 4; o > 0; o >>= 1) s += __shfl_down_sync(0xffffffffu, s, o);
        if (lane == 0) atomicAdd(lap_slot, s);
    }
}

// ---------------------------------------------------------------------------
extern "C" void kernel_launch(void* const* d_in, const int* in_sizes, int n_in,
                              void* d_out, int out_size)
{
    const float* vertices = (const float*)d_in[0];
    const float* joints   = (const float*)d_in[1];
    const float* skin     = (const float*)d_in[2];
    const float* j0       = (const float*)d_in[3];
    const float* j2       = (const float*)d_in[4];
    const float* j3       = (const float*)d_in[5];
    const float* j4       = (const float*)d_in[6];
    const float* j5       = (const float*)d_in[7];
    const float* disp     = (const float*)d_in[8];
    const float* rdis     = (const float*)d_in[9];
    const int*   faces    = (const int*)d_in[10];

    int V = in_sizes[0] / 3;
    int F = in_sizes[10] / 3;
    float* out = (float*)d_out;
    int B = (out_size - 1) / (V * 3);
    float* lap_slot = out + (out_size - 1);

    k_skin<<<(V + SKIN_B - 1) / SKIN_B, SKIN_B>>>(
        vertices, skin, joints, j0, j2, j3, j4, j5, disp, rdis,
        out, lap_slot, V);

    // Fused faces + broadcast. copy slots = grid/4, face slots = 3*grid/4.
    int n4 = (V * 3) / 4;
    int nCopy  = (n4 + 255) / 256;
    int nFace  = (F + 255) / 256;
    int gridCopy = nCopy * 4;
    int gridFace = ((nFace + 2) / 3) * 4;
    int grid = gridCopy > gridFace ? gridCopy : gridFace;
    k_faces_bcast<<<grid, 256>>>(faces, F, out, V, B);

    int half = (V + 1) >> 1;
    k_lap<<<(half + 255) / 256, 256>>>(lap_slot, V);
}

// round 5
// speedup vs baseline: 1.6559x; 1.6559x over previous
#include <cuda_runtime.h>
#include <math.h>

#define JN 23
#define VMAX 400000

// Scratch (device globals — no allocation allowed)
__device__ float  g_A[JN * 12];     // per-joint 3x4 skinning matrices
__device__ float  g_off[3];         // random_dis + displacement
__device__ float4 g_verts[VMAX];    // posed verts (xyz, pad)
__device__ float4 g_nsum[VMAX];     // neighbor sum xyz + degree in .w

// ---------------------------------------------------------------------------
// Kernel 1: rig math, run ONCE (1 block, 32 threads). Lanes 0..22 do
// Rodrigues in parallel; lane 0 walks the serial chain in SHARED memory
// (dynamic parent indexing would spill a local array).
// ---------------------------------------------------------------------------
__global__ void k_rig(const float* __restrict__ joints,
                      const float* __restrict__ j0in,
                      const float* __restrict__ j2in,
                      const float* __restrict__ j3in,
                      const float* __restrict__ j4in,
                      const float* __restrict__ j5in,
                      const float* __restrict__ disp,
                      const float* __restrict__ rdis)
{
    __shared__ float sM[JN][12];
    __shared__ float chain[JN][12];
    const int lane = threadIdx.x;
    const float HALF_PI = 1.5707963267948966f;
    const int PAR[JN] = {-1,0,1,1,3,4,5,4,7,4,9,1,11,12,13,12,15,12,17,0,19,0,21};

    if (lane < JN) {
        float px = 0.f, py = 0.f, pz = 0.f;
        if (lane == 0)       { px = j0in[0]; py = j0in[1]; pz = j0in[2]; }
        else if (lane == 3)  { px = HALF_PI*tanhf(j2in[0]); py = HALF_PI*tanhf(j2in[1]); pz = HALF_PI*tanhf(j2in[2]); }
        else if (lane == 4)  { px = HALF_PI*tanhf(j3in[0]); py = HALF_PI*tanhf(j3in[1]); pz = HALF_PI*tanhf(j3in[2]); }
        else if (lane == 11) { px = HALF_PI*tanhf(j4in[0]); py = HALF_PI*tanhf(j4in[1]); pz = HALF_PI*tanhf(j4in[2]); }
        else if (lane == 12) { px = HALF_PI*tanhf(j5in[0]); py = HALF_PI*tanhf(j5in[1]); pz = HALF_PI*tanhf(j5in[2]); }

        float ang = sqrtf(px*px + py*py + pz*pz) + 1e-8f;
        float ax = px/ang, ay = py/ang, az = pz/ang;
        float K[9]  = {0.f, -az, ay,  az, 0.f, -ax,  -ay, ax, 0.f};
        float K2[9];
        #pragma unroll
        for (int r = 0; r < 3; r++)
            #pragma unroll
            for (int c = 0; c < 3; c++) {
                float s = 0.f;
                #pragma unroll
                for (int t = 0; t < 3; t++) s += K[r*3+t] * K[t*3+c];
                K2[r*3+c] = s;
            }
        float sn = sinf(ang), cs = cosf(ang);
        float R[9];
        #pragma unroll
        for (int e = 0; e < 9; e++) {
            float eye = (e == 0 || e == 4 || e == 8) ? 1.0f : 0.0f;
            R[e] = eye + sn * K[e] + (1.0f - cs) * K2[e];
        }
        float rel[3];
        #pragma unroll
        for (int k = 0; k < 3; k++) {
            rel[k] = joints[lane*3 + k];
            if (lane > 0) rel[k] -= joints[PAR[lane]*3 + k];
        }
        sM[lane][0]=R[0]; sM[lane][1]=R[1]; sM[lane][2] =R[2]; sM[lane][3] =rel[0];
        sM[lane][4]=R[3]; sM[lane][5]=R[4]; sM[lane][6] =R[5]; sM[lane][7] =rel[1];
        sM[lane][8]=R[6]; sM[lane][9]=R[7]; sM[lane][10]=R[8]; sM[lane][11]=rel[2];
    }
    __syncwarp();

    if (lane == 0) {
        #pragma unroll
        for (int e = 0; e < 12; e++) chain[0][e] = sM[0][e];
        for (int i = 1; i < JN; i++) {
            const float* P = chain[PAR[i]];
            const float* M = sM[i];
            float* C = chain[i];
            #pragma unroll
            for (int r = 0; r < 3; r++) {
                #pragma unroll
                for (int cc = 0; cc < 3; cc++) {
                    C[r*4+cc] = P[r*4+0]*M[0*4+cc] + P[r*4+1]*M[1*4+cc] + P[r*4+2]*M[2*4+cc];
                }
                C[r*4+3] = P[r*4+0]*M[3] + P[r*4+1]*M[7] + P[r*4+2]*M[11] + P[r*4+3];
            }
        }
    }
    __syncwarp();

    // lanes 0..22 write A_i in parallel
    if (lane < JN) {
        float jx = joints[lane*3+0], jy = joints[lane*3+1], jz = joints[lane*3+2];
        #pragma unroll
        for (int r = 0; r < 3; r++) {
            float corr = chain[lane][r*4+0]*jx + chain[lane][r*4+1]*jy + chain[lane][r*4+2]*jz;
            g_A[lane*12 + r*4 + 0] = chain[lane][r*4+0];
            g_A[lane*12 + r*4 + 1] = chain[lane][r*4+1];
            g_A[lane*12 + r*4 + 2] = chain[lane][r*4+2];
            g_A[lane*12 + r*4 + 3] = chain[lane][r*4+3] - corr;
        }
    }
    if (lane < 3) g_off[lane] = rdis[lane] + disp[lane];
}

// ---------------------------------------------------------------------------
// Kernel 2: skinning with coalesced smem staging of the weight tile (R3,
// measured good). tile 16B-aligned for float4 staging.
// ---------------------------------------------------------------------------
#define SKIN_B 256
__global__ void __launch_bounds__(SKIN_B)
k_skin(const float* __restrict__ verts_in,
       const float* __restrict__ skin,
       float* __restrict__ out,
       float* __restrict__ lap_slot,
       int V)
{
    __shared__ __align__(16) float tile[SKIN_B * JN];  // 23.5 KB, stride-23 reads
    __shared__ float sA[JN * 12];
    __shared__ float soff[3];

    for (int i = threadIdx.x; i < JN * 12; i += SKIN_B) sA[i] = g_A[i];
    if (threadIdx.x < 3) soff[threadIdx.x] = g_off[threadIdx.x];

    const int base = blockIdx.x * SKIN_B;
    const int nv   = min(SKIN_B, V - base);

    if (nv == SKIN_B) {
        const float4* src = reinterpret_cast<const float4*>(skin + (size_t)base * JN);
        float4* dst = reinterpret_cast<float4*>(tile);
        #pragma unroll
        for (int i = threadIdx.x; i < SKIN_B * JN / 4; i += SKIN_B) dst[i] = src[i];
    } else {
        const float* src = skin + (size_t)base * JN;
        for (int i = threadIdx.x; i < nv * JN; i += SKIN_B) tile[i] = src[i];
    }
    __syncthreads();

    const int v = base + threadIdx.x;
    if (v == 0) *lap_slot = 0.0f;
    if (threadIdx.x >= nv) return;

    float T[12];
    #pragma unroll
    for (int e = 0; e < 12; e++) T[e] = 0.0f;

    const float* s = tile + threadIdx.x * JN;
    #pragma unroll
    for (int j = 0; j < JN; j++) {
        float w = s[j];
        #pragma unroll
        for (int e = 0; e < 12; e++) T[e] += w * sA[j*12 + e];
    }

    float x = verts_in[3*v+0], y = verts_in[3*v+1], z = verts_in[3*v+2];
    float px = T[0]*x + T[1]*y + T[2] *z + T[3]  + soff[0];
    float py = T[4]*x + T[5]*y + T[6] *z + T[7]  + soff[1];
    float pz = T[8]*x + T[9]*y + T[10]*z + T[11] + soff[2];

    g_verts[v] = make_float4(px, py, pz, 0.0f);
    g_nsum[v]  = make_float4(0.0f, 0.0f, 0.0f, 0.0f);

    out[3*v+0] = px;
    out[3*v+1] = py;
    out[3*v+2] = pz;
}

// ---------------------------------------------------------------------------
// Kernel 3 (fused): face scatter (LTS-atomic bound, 2 faces/thread for MLP)
// interleaved with the batch broadcast (DRAM bound) via blockIdx % 4.
// ---------------------------------------------------------------------------
__device__ __forceinline__ void red4(float4* p, float x, float y, float z, float w)
{
    asm volatile("red.global.add.v4.f32 [%0], {%1, %2, %3, %4};"
                 :: "l"(p), "f"(x), "f"(y), "f"(z), "f"(w) : "memory");
}

__device__ __forceinline__ void face_scatter(const int* __restrict__ faces, int f)
{
    int a = __ldg(&faces[3*f+0]);
    int b = __ldg(&faces[3*f+1]);
    int c = __ldg(&faces[3*f+2]);
    float4 va = __ldg(&g_verts[a]);
    float4 vb = __ldg(&g_verts[b]);
    float4 vc = __ldg(&g_verts[c]);
    red4(&g_nsum[a], vb.x + vc.x, vb.y + vc.y, vb.z + vc.z, 2.0f);
    red4(&g_nsum[b], va.x + vc.x, va.y + vc.y, va.z + vc.z, 2.0f);
    red4(&g_nsum[c], va.x + vb.x, va.y + vb.y, va.z + vb.z, 2.0f);
}

__global__ void __launch_bounds__(256)
k_faces_bcast(const int* __restrict__ faces, int F,
              float* __restrict__ out, int V, int B)
{
    if ((blockIdx.x & 3) == 0) {
        // ---- copy block: broadcast batch 0 -> batches 1..B-1 ----
        const int cid = blockIdx.x >> 2;
        const int n4 = (V * 3) / 4;
        const int i = cid * 256 + threadIdx.x;
        if (i < n4) {
            float4 val = __ldg(reinterpret_cast<const float4*>(out) + i);
            const size_t stride4 = (size_t)(V * 3) / 4;
            float4* o = reinterpret_cast<float4*>(out);
            #pragma unroll 4
            for (int b = 1; b < B; b++) o[(size_t)b * stride4 + i] = val;
        }
    } else {
        // ---- face block: 2 faces per thread (512 per block) ----
        const int fid = blockIdx.x - ((int)blockIdx.x >> 2) - 1;
        const int f0 = fid * 512 + threadIdx.x;
        const int f1 = f0 + 256;
        if (f1 < F) {
            // both in range: issue both load groups back-to-back (MLP)
            int a0 = __ldg(&faces[3*f0+0]), b0 = __ldg(&faces[3*f0+1]), c0 = __ldg(&faces[3*f0+2]);
            int a1 = __ldg(&faces[3*f1+0]), b1 = __ldg(&faces[3*f1+1]), c1 = __ldg(&faces[3*f1+2]);
            float4 va0 = __ldg(&g_verts[a0]), vb0 = __ldg(&g_verts[b0]), vc0 = __ldg(&g_verts[c0]);
            float4 va1 = __ldg(&g_verts[a1]), vb1 = __ldg(&g_verts[b1]), vc1 = __ldg(&g_verts[c1]);
            red4(&g_nsum[a0], vb0.x + vc0.x, vb0.y + vc0.y, vb0.z + vc0.z, 2.0f);
            red4(&g_nsum[b0], va0.x + vc0.x, va0.y + vc0.y, va0.z + vc0.z, 2.0f);
            red4(&g_nsum[c0], va0.x + vb0.x, va0.y + vb0.y, va0.z + vb0.z, 2.0f);
            red4(&g_nsum[a1], vb1.x + vc1.x, vb1.y + vc1.y, vb1.z + vc1.z, 2.0f);
            red4(&g_nsum[b1], va1.x + vc1.x, va1.y + vc1.y, va1.z + vc1.z, 2.0f);
            red4(&g_nsum[c1], va1.x + vb1.x, va1.y + vb1.y, va1.z + vb1.z, 2.0f);
        } else {
            if (f0 < F) face_scatter(faces, f0);
        }
    }
}

// ---------------------------------------------------------------------------
// Kernel 4: Laplacian reduction. 2 vertices per thread (v, v+half), all four
// loads issued up-front (MLP=4); 782 blocks keeps occupancy high.
// ---------------------------------------------------------------------------
__global__ void __launch_bounds__(256)
k_lap(float* __restrict__ lap_slot, int V)
{
    const int half = (V + 1) >> 1;
    const int v1 = blockIdx.x * blockDim.x + threadIdx.x;
    const int v2 = v1 + half;

    float s = 0.0f;
    if (v1 < half) {
        float4 p1 = __ldg(&g_verts[v1]);
        float4 n1 = __ldg(&g_nsum[v1]);
        bool ok2 = (v2 < V);
        float4 p2 = ok2 ? __ldg(&g_verts[v2]) : make_float4(0,0,0,0);
        float4 n2 = ok2 ? __ldg(&g_nsum[v2]) : make_float4(0,0,0,1);

        float d1 = fmaxf(n1.w, 1.0f);
        float lx = p1.x - n1.x / d1;
        float ly = p1.y - n1.y / d1;
        float lz = p1.z - n1.z / d1;
        s = lx*lx + ly*ly + lz*lz;

        float d2 = fmaxf(n2.w, 1.0f);
        float mx = p2.x - n2.x / d2;
        float my = p2.y - n2.y / d2;
        float mz = p2.z - n2.z / d2;
        s += mx*mx + my*my + mz*mz;
    }

    #pragma unroll
    for (int o = 16; o > 0; o >>= 1) s += __shfl_down_sync(0xffffffffu, s, o);

    __shared__ float ws[8];
    int lane = threadIdx.x & 31, w = threadIdx.x >> 5;
    if (lane == 0) ws[w] = s;
    __syncthreads();
    if (w == 0) {
        s = (lane < (int)(blockDim.x >> 5)) ? ws[lane] : 0.0f;
        #pragma unroll
        for (int o = 4; o > 0; o >>= 1) s += __shfl_down_sync(0xffffffffu, s, o);
        if (lane == 0) atomicAdd(lap_slot, s);
    }
}

// ---------------------------------------------------------------------------
extern "C" void kernel_launch(void* const* d_in, const int* in_sizes, int n_in,
                              void* d_out, int out_size)
{
    const float* vertices = (const float*)d_in[0];
    const float* joints   = (const float*)d_in[1];
    const float* skin     = (const float*)d_in[2];
    const float* j0       = (const float*)d_in[3];
    const float* j2       = (const float*)d_in[4];
    const float* j3       = (const float*)d_in[5];
    const float* j4       = (const float*)d_in[6];
    const float* j5       = (const float*)d_in[7];
    const float* disp     = (const float*)d_in[8];
    const float* rdis     = (const float*)d_in[9];
    const int*   faces    = (const int*)d_in[10];

    int V = in_sizes[0] / 3;
    int F = in_sizes[10] / 3;
    float* out = (float*)d_out;
    int B = (out_size - 1) / (V * 3);
    float* lap_slot = out + (out_size - 1);

    k_rig<<<1, 32>>>(joints, j0, j2, j3, j4, j5, disp, rdis);
    k_skin<<<(V + SKIN_B - 1) / SKIN_B, SKIN_B>>>(vertices, skin, out, lap_slot, V);

    // Fused faces + broadcast. copy slots = grid/4, face slots = 3*grid/4,
    // face blocks process 512 faces each.
    int n4 = (V * 3) / 4;
    int nCopy  = (n4 + 255) / 256;                  // 1172
    int nFaceB = (F + 511) / 512;                   // 1563
    int gridCopy = nCopy * 4;                       // 4688
    int gridFace = ((nFaceB + 2) / 3) * 4;          // 2084
    int grid = gridCopy > gridFace ? gridCopy : gridFace;
    k_faces_bcast<<<grid, 256>>>(faces, F, out, V, B);

    int half = (V + 1) >> 1;
    k_lap<<<(half + 255) / 256, 256>>>(lap_slot, V);
}